// round 7
// baseline (speedup 1.0000x reference)
#include <cuda_runtime.h>
#include <cstdint>

#define DIMC   256
#define INNER  512
#define HH     56
#define HW     3136        // 56*56
#define BATCH  16

// GEMM tiles
#define BM 128
#define BN 112
#define BK 16
#define AST 20     // As row stride (floats): banks = (20g+tig)%32 all-distinct
#define BST 120    // Bs row stride (floats): banks = (24tig+g)%32 all-distinct

#define SD 68      // attention smem row stride ([token][d])

// ---------------- scratch (static device globals; no allocation) ----------------
__device__ float g_yq[(size_t)BATCH * DIMC  * HW];
__device__ float g_yk[(size_t)BATCH * DIMC  * HW];
__device__ float g_yv[(size_t)BATCH * DIMC  * HW];
__device__ float g_q[(size_t)BATCH * INNER * HW];
__device__ float g_k[(size_t)BATCH * INNER * HW];
__device__ float g_v[(size_t)BATCH * INNER * HW];
__device__ float g_o[(size_t)BATCH * INNER * HW];

// ---------------- fused 3x depthwise 3x3 conv + BN (eval) ----------------
__global__ void dw_bn3_kernel(const float* __restrict__ x,
                              const float* __restrict__ qw, const float* __restrict__ qg,
                              const float* __restrict__ qb, const float* __restrict__ qm,
                              const float* __restrict__ qv,
                              const float* __restrict__ kw, const float* __restrict__ kg,
                              const float* __restrict__ kb, const float* __restrict__ km,
                              const float* __restrict__ kv,
                              const float* __restrict__ vw, const float* __restrict__ vg,
                              const float* __restrict__ vb, const float* __restrict__ vm,
                              const float* __restrict__ vv)
{
    int idx = blockIdx.x * blockDim.x + threadIdx.x;
    int hw  = idx % HW;
    int bc  = idx / HW;
    int c   = bc % DIMC;
    int h   = hw / HH;
    int wq  = hw - h * HH;

    float qs = qg[c] * rsqrtf(qv[c] + 1e-5f);
    float qbe = qb[c] - qm[c] * qs;
    float ks = kg[c] * rsqrtf(kv[c] + 1e-5f);
    float kbe = kb[c] - km[c] * ks;
    float vs = vg[c] * rsqrtf(vv[c] + 1e-5f);
    float vbe = vb[c] - vm[c] * vs;

    const float* xp = x + (size_t)bc * HW;
    const float* qwp = qw + c * 9;
    const float* kwp = kw + c * 9;
    const float* vwp = vw + c * 9;

    float qa = 0.f, ka = 0.f, va = 0.f;
#pragma unroll
    for (int kh = 0; kh < 3; kh++) {
        int ih = h + kh - 1;
        if (ih < 0 || ih >= HH) continue;
#pragma unroll
        for (int kw2 = 0; kw2 < 3; kw2++) {
            int iw = wq + kw2 - 1;
            if (iw < 0 || iw >= HH) continue;
            float xv = xp[ih * HH + iw];
            int wi = kh * 3 + kw2;
            qa = fmaf(xv, qwp[wi], qa);
            ka = fmaf(xv, kwp[wi], ka);
            va = fmaf(xv, vwp[wi], va);
        }
    }
    g_yq[idx] = qa * qs + qbe;
    g_yk[idx] = ka * ks + kbe;
    g_yv[idx] = va * vs + vbe;
}

// ---------------- TF32 tensor-core GEMM, cp.async double-buffered ----------------
// C[b][m][p] = sum_k W[m][k] * SRC[b][k][p] (+bias)
// Block 128x112, BK=16, 256 threads (8 warps as 4x2), warp tile 32x56 = 2x7 m16n8k8.

__device__ __forceinline__ uint32_t to_tf32(float x) {
    uint32_t u;
    asm("cvt.rna.tf32.f32 %0, %1;" : "=r"(u) : "f"(x));
    return u;
}

__device__ __forceinline__ void mma_tf32(float* d, const uint32_t* a, const uint32_t* b) {
    asm volatile(
        "mma.sync.aligned.m16n8k8.row.col.f32.tf32.tf32.f32 "
        "{%0,%1,%2,%3}, {%4,%5,%6,%7}, {%8,%9}, {%0,%1,%2,%3};\n"
        : "+f"(d[0]), "+f"(d[1]), "+f"(d[2]), "+f"(d[3])
        : "r"(a[0]), "r"(a[1]), "r"(a[2]), "r"(a[3]), "r"(b[0]), "r"(b[1]));
}

__device__ __forceinline__ void cp16(uint32_t dst, const void* src) {
    asm volatile("cp.async.cg.shared.global [%0], [%1], 16;\n" :: "r"(dst), "l"(src));
}
__device__ __forceinline__ void cpCommit() {
    asm volatile("cp.async.commit_group;\n" ::);
}
template<int N> __device__ __forceinline__ void cpWait() {
    asm volatile("cp.async.wait_group %0;\n" :: "n"(N));
}

__global__ void __launch_bounds__(256, 2)
gemm_tf32_kernel(const float* __restrict__ W,
                 const float* __restrict__ bias,
                 const float* __restrict__ src,
                 float* __restrict__ dst,
                 int Kdim)
{
    __shared__ float As[2][BM * AST];   // [m][k] raw f32
    __shared__ float Bs[2][BK * BST];   // [k][n] raw f32

    int b     = blockIdx.z;
    int nBase = blockIdx.x * BN;
    int mBase = blockIdx.y * BM;

    const float* Bb = src + (size_t)b * Kdim * HW;

    int t    = threadIdx.x;
    int wid  = t >> 5;
    int lane = t & 31;
    int g    = lane >> 2;
    int tig  = lane & 3;
    int m0   = (wid >> 1) * 32;   // 0,32,64,96
    int n0   = (wid & 1) * 56;    // 0,56

    // A staging: thread t owns row m = t>>1, k-half = (t&1)*8 (two float4)
    int aRow  = t >> 1;
    int aKoff = (t & 1) << 3;
    const float* aPtr = W + (size_t)(mBase + aRow) * Kdim + aKoff;

    uint32_t sAb[2], sBb[2];
    sAb[0] = (uint32_t)__cvta_generic_to_shared(&As[0][0]);
    sAb[1] = (uint32_t)__cvta_generic_to_shared(&As[1][0]);
    sBb[0] = (uint32_t)__cvta_generic_to_shared(&Bs[0][0]);
    sBb[1] = (uint32_t)__cvta_generic_to_shared(&Bs[1][0]);
    uint32_t aDst = (uint32_t)(aRow * AST + aKoff) * 4;

    // B load mapping: 448 float4 chunks per stage (16 rows x 28 chunks), 256 threads
    int bRow0 = t / 28, bC0 = t - bRow0 * 28;
    int bi1   = t + 256;
    int bRow1 = bi1 / 28, bC1 = bi1 - bRow1 * 28;
    bool bAct1 = (bi1 < 448);

    float acc[2][7][4];
#pragma unroll
    for (int i = 0; i < 2; i++)
#pragma unroll
        for (int j = 0; j < 7; j++)
#pragma unroll
            for (int r = 0; r < 4; r++) acc[i][j][r] = 0.f;

    int nStages = Kdim >> 4;

#define LOAD_STAGE(K0, BUF)                                                         \
    {                                                                               \
        cp16(sAb[BUF] + aDst,      aPtr + (K0));                                    \
        cp16(sAb[BUF] + aDst + 16, aPtr + (K0) + 4);                                \
        cp16(sBb[BUF] + bRow0 * (BST * 4) + bC0 * 16,                               \
             Bb + (size_t)((K0) + bRow0) * HW + nBase + bC0 * 4);                   \
        if (bAct1)                                                                  \
            cp16(sBb[BUF] + bRow1 * (BST * 4) + bC1 * 16,                           \
                 Bb + (size_t)((K0) + bRow1) * HW + nBase + bC1 * 4);               \
    }

#define COMPUTE_STAGE(BUF)                                                          \
    {                                                                               \
        _Pragma("unroll")                                                           \
        for (int kk = 0; kk < 2; kk++) {                                            \
            int kb = kk * 8;                                                        \
            uint32_t af[2][4];                                                      \
            uint32_t bf[7][2];                                                      \
            _Pragma("unroll")                                                       \
            for (int im = 0; im < 2; im++) {                                        \
                const float* ap = &As[BUF][(m0 + 16 * im + g) * AST + kb + tig];    \
                af[im][0] = to_tf32(ap[0]);                                         \
                af[im][1] = to_tf32(ap[8 * AST]);                                   \
                af[im][2] = to_tf32(ap[4]);                                         \
                af[im][3] = to_tf32(ap[8 * AST + 4]);                               \
            }                                                                       \
            _Pragma("unroll")                                                       \
            for (int jn = 0; jn < 7; jn++) {                                        \
                const float* bp = &Bs[BUF][(kb + tig) * BST + n0 + 8 * jn + g];     \
                bf[jn][0] = to_tf32(bp[0]);                                         \
                bf[jn][1] = to_tf32(bp[4 * BST]);                                   \
            }                                                                       \
            _Pragma("unroll")                                                       \
            for (int im = 0; im < 2; im++)                                          \
                _Pragma("unroll")                                                   \
                for (int jn = 0; jn < 7; jn++)                                      \
                    mma_tf32(acc[im][jn], af[im], bf[jn]);                          \
        }                                                                           \
    }

    LOAD_STAGE(0, 0);
    cpCommit();

    int buf = 0;
    for (int s = 0; s < nStages; s++) {
        if (s + 1 < nStages) {
            LOAD_STAGE((s + 1) << 4, buf ^ 1);
            cpCommit();
            cpWait<1>();
        } else {
            cpWait<0>();
        }
        __syncthreads();
        COMPUTE_STAGE(buf);
        __syncthreads();
        buf ^= 1;
    }

    // ---- epilogue ----
    float* Cb = dst + (size_t)b * (gridDim.y * BM) * HW;
#pragma unroll
    for (int im = 0; im < 2; im++) {
#pragma unroll
        for (int r2 = 0; r2 < 2; r2++) {
            int m = mBase + m0 + 16 * im + g + 8 * r2;
            float bi = bias ? bias[m] : 0.f;
#pragma unroll
            for (int jn = 0; jn < 7; jn++) {
                int n = nBase + n0 + 8 * jn + 2 * tig;
                float2 val = make_float2(acc[im][jn][2 * r2] + bi,
                                         acc[im][jn][2 * r2 + 1] + bi);
                *(float2*)(Cb + (size_t)m * HW + n) = val;
            }
        }
    }
#undef LOAD_STAGE
#undef COMPUTE_STAGE
}

// ---------------- windowed attention: one CTA per (b, head, window) ----------------
// smem layout [token][d] stride SD=68: float4 K loads + float4 q broadcasts in QK,
// float2 V loads in AV, probabilities kept in registers (shfl broadcast).
// Warps 0..6 own rows 7w..7w+6.
__global__ void attn_kernel(const float* __restrict__ pos_emb)
{
    __shared__ float q_s[49 * SD];    // q[i][d], reused for o[i][d]
    __shared__ float k_s[49 * SD];    // k[j][d]
    __shared__ float v_s[49 * SD];    // v[j][d]
    __shared__ float bias_s[169];

    int t   = threadIdx.x;
    int win = blockIdx.x;
    int h   = blockIdx.y;
    int b   = blockIdx.z;

    int base_hw = ((win >> 3) * 7) * HH + (win & 7) * 7;
    size_t gbase = ((size_t)b * INNER + h * 64) * HW;
    const float* qb = g_q + gbase;
    const float* kb = g_k + gbase;
    const float* vb = g_v + gbase;

    // gather: global reads d-major (coalesced-ish runs of 7), smem writes [j][d]
    for (int e = t; e < 3136; e += 256) {
        int d = e / 49;
        int j = e - d * 49;
        int off = base_hw + (j / 7) * HH + (j % 7);
        size_t gi = (size_t)d * HW + off;
        int si = j * SD + d;
        q_s[si] = qb[gi];
        k_s[si] = kb[gi];
        v_s[si] = vb[gi];
    }
    if (t < 169) bias_s[t] = pos_emb[t * 8 + h];
    __syncthreads();

    int wid  = t >> 5;
    int lane = t & 31;

    float p0[7], p1[7];

    if (wid < 7) {
        int iBase = wid * 7;
        int j0 = lane;
        int j1 = lane + 32;
        int jm = (j1 < 49) ? j1 : 48;

        // ---- QK^T: float4 over d ----
        float a0[7], a1[7];
#pragma unroll
        for (int r = 0; r < 7; r++) { a0[r] = 0.f; a1[r] = 0.f; }

#pragma unroll 4
        for (int ds = 0; ds < 16; ds++) {
            float4 kc0 = *(const float4*)&k_s[j0 * SD + 4 * ds];
            float4 kc1 = *(const float4*)&k_s[jm * SD + 4 * ds];
#pragma unroll
            for (int r = 0; r < 7; r++) {
                float4 qd = *(const float4*)&q_s[(iBase + r) * SD + 4 * ds];
                a0[r] = fmaf(qd.x, kc0.x, a0[r]);
                a0[r] = fmaf(qd.y, kc0.y, a0[r]);
                a0[r] = fmaf(qd.z, kc0.z, a0[r]);
                a0[r] = fmaf(qd.w, kc0.w, a0[r]);
                a1[r] = fmaf(qd.x, kc1.x, a1[r]);
                a1[r] = fmaf(qd.y, kc1.y, a1[r]);
                a1[r] = fmaf(qd.z, kc1.z, a1[r]);
                a1[r] = fmaf(qd.w, kc1.w, a1[r]);
            }
        }

        // ---- bias + softmax (probs -> registers) ----
        int xj0 = j0 / 7, yj0 = j0 - xj0 * 7;
        int xj1 = jm / 7, yj1 = jm - xj1 * 7;
#pragma unroll
        for (int r = 0; r < 7; r++) {
            int i = iBase + r;
            int xi = i / 7, yi = i - xi * 7;
            float v0 = a0[r] * 0.125f + bias_s[(xj0 - xi + 6) * 13 + (yj0 - yi + 6)];
            float v1;
            if (j1 < 49)
                v1 = a1[r] * 0.125f + bias_s[(xj1 - xi + 6) * 13 + (yj1 - yi + 6)];
            else
                v1 = -1e30f;

            float mx = fmaxf(v0, v1);
#pragma unroll
            for (int o = 16; o; o >>= 1) mx = fmaxf(mx, __shfl_xor_sync(0xffffffffu, mx, o));
            float e0 = __expf(v0 - mx);
            float e1 = (j1 < 49) ? __expf(v1 - mx) : 0.f;
            float s = e0 + e1;
#pragma unroll
            for (int o = 16; o; o >>= 1) s += __shfl_xor_sync(0xffffffffu, s, o);
            float inv = 1.f / s;
            p0[r] = e0 * inv;
            p1[r] = e1 * inv;
        }

        // ---- A @ V: lane owns d = {2*lane, 2*lane+1}; probs via shfl ----
        float oA[7], oB[7];
#pragma unroll
        for (int r = 0; r < 7; r++) { oA[r] = 0.f; oB[r] = 0.f; }

        int dOff = 2 * lane;
#pragma unroll 7
        for (int j = 0; j < 49; j++) {
            float2 vc = *(const float2*)&v_s[j * SD + dOff];
            if (j < 32) {
#pragma unroll
                for (int r = 0; r < 7; r++) {
                    float pv = __shfl_sync(0xffffffffu, p0[r], j);
                    oA[r] = fmaf(pv, vc.x, oA[r]);
                    oB[r] = fmaf(pv, vc.y, oB[r]);
                }
            } else {
#pragma unroll
                for (int r = 0; r < 7; r++) {
                    float pv = __shfl_sync(0xffffffffu, p1[r], j - 32);
                    oA[r] = fmaf(pv, vc.x, oA[r]);
                    oB[r] = fmaf(pv, vc.y, oB[r]);
                }
            }
        }
#pragma unroll
        for (int r = 0; r < 7; r++) {
            *(float2*)&q_s[(iBase + r) * SD + dOff] = make_float2(oA[r], oB[r]);
        }
    }
    __syncthreads();

    // scatter: smem reads [j][d], global writes d-major
    float* ob = g_o + gbase;
    for (int e = t; e < 3136; e += 256) {
        int d = e / 49;
        int j = e - d * 49;
        ob[(size_t)d * HW + base_hw + (j / 7) * HH + (j % 7)] = q_s[j * SD + d];
    }
}

// ---------------- launch ----------------
extern "C" void kernel_launch(void* const* d_in, const int* in_sizes, int n_in,
                              void* d_out, int out_size)
{
    (void)in_sizes; (void)n_in; (void)out_size;
    const float* x      = (const float*)d_in[0];
    const float* q_dw   = (const float*)d_in[1];
    const float* q_g    = (const float*)d_in[2];
    const float* q_b    = (const float*)d_in[3];
    const float* q_m    = (const float*)d_in[4];
    const float* q_v    = (const float*)d_in[5];
    const float* q_pw   = (const float*)d_in[6];
    const float* k_dw   = (const float*)d_in[7];
    const float* k_g    = (const float*)d_in[8];
    const float* k_b    = (const float*)d_in[9];
    const float* k_m    = (const float*)d_in[10];
    const float* k_v    = (const float*)d_in[11];
    const float* k_pw   = (const float*)d_in[12];
    const float* v_dw   = (const float*)d_in[13];
    const float* v_g    = (const float*)d_in[14];
    const float* v_b    = (const float*)d_in[15];
    const float* v_m    = (const float*)d_in[16];
    const float* v_v    = (const float*)d_in[17];
    const float* v_pw   = (const float*)d_in[18];
    const float* pos    = (const float*)d_in[19];
    const float* out_w  = (const float*)d_in[20];
    const float* out_b  = (const float*)d_in[21];
    float* out          = (float*)d_out;

    float *yq, *yk, *yv, *q, *k, *v, *o;
    cudaGetSymbolAddress((void**)&yq, g_yq);
    cudaGetSymbolAddress((void**)&yk, g_yk);
    cudaGetSymbolAddress((void**)&yv, g_yv);
    cudaGetSymbolAddress((void**)&q,  g_q);
    cudaGetSymbolAddress((void**)&k,  g_k);
    cudaGetSymbolAddress((void**)&v,  g_v);
    cudaGetSymbolAddress((void**)&o,  g_o);

    const int dwBlocks = (BATCH * DIMC * HW) / 256;
    dim3 gemmGridQKV(HW / BN, INNER / BM, BATCH);   // (28, 4, 16)
    dim3 gemmGridOut(HW / BN, DIMC / BM, BATCH);    // (28, 2, 16)
    dim3 attnGrid(64, 8, BATCH);

    dw_bn3_kernel<<<dwBlocks, 256>>>(x,
        q_dw, q_g, q_b, q_m, q_v,
        k_dw, k_g, k_b, k_m, k_v,
        v_dw, v_g, v_b, v_m, v_v);
    gemm_tf32_kernel<<<gemmGridQKV, 256>>>(q_pw, nullptr, yq, q, DIMC);
    gemm_tf32_kernel<<<gemmGridQKV, 256>>>(k_pw, nullptr, yk, k, DIMC);
    gemm_tf32_kernel<<<gemmGridQKV, 256>>>(v_pw, nullptr, yv, v, DIMC);
    attn_kernel<<<attnGrid, 256>>>(pos);
    gemm_tf32_kernel<<<gemmGridOut, 256>>>(out_w, out_b, o, out, INNER);
}

// round 9
// speedup vs baseline: 1.3926x; 1.3926x over previous
#include <cuda_runtime.h>
#include <cstdint>

#define DIMC   256
#define INNER  512
#define HH     56
#define HW     3136        // 56*56
#define BATCH  16

// GEMM tiles
#define BM 128
#define BN 112
#define BK 16
#define AST 20     // As row stride (floats): banks = (20g+tig)%32 all-distinct
#define BST 120    // Bs row stride (floats): banks = (24tig+g)%32 all-distinct

// ---------------- scratch (static device globals; no allocation) ----------------
__device__ float g_yq[(size_t)BATCH * DIMC  * HW];
__device__ float g_yk[(size_t)BATCH * DIMC  * HW];
__device__ float g_yv[(size_t)BATCH * DIMC  * HW];
__device__ float g_q[(size_t)BATCH * INNER * HW];
__device__ float g_k[(size_t)BATCH * INNER * HW];
__device__ float g_v[(size_t)BATCH * INNER * HW];
__device__ float g_o[(size_t)BATCH * INNER * HW];

// ---------------- fused 3x depthwise 3x3 conv + BN (eval) ----------------
__global__ void dw_bn3_kernel(const float* __restrict__ x,
                              const float* __restrict__ qw, const float* __restrict__ qg,
                              const float* __restrict__ qb, const float* __restrict__ qm,
                              const float* __restrict__ qv,
                              const float* __restrict__ kw, const float* __restrict__ kg,
                              const float* __restrict__ kb, const float* __restrict__ km,
                              const float* __restrict__ kv,
                              const float* __restrict__ vw, const float* __restrict__ vg,
                              const float* __restrict__ vb, const float* __restrict__ vm,
                              const float* __restrict__ vv)
{
    int idx = blockIdx.x * blockDim.x + threadIdx.x;
    int hw  = idx % HW;
    int bc  = idx / HW;
    int c   = bc % DIMC;
    int h   = hw / HH;
    int wq  = hw - h * HH;

    float qs = qg[c] * rsqrtf(qv[c] + 1e-5f);
    float qbe = qb[c] - qm[c] * qs;
    float ks = kg[c] * rsqrtf(kv[c] + 1e-5f);
    float kbe = kb[c] - km[c] * ks;
    float vs = vg[c] * rsqrtf(vv[c] + 1e-5f);
    float vbe = vb[c] - vm[c] * vs;

    const float* xp = x + (size_t)bc * HW;
    const float* qwp = qw + c * 9;
    const float* kwp = kw + c * 9;
    const float* vwp = vw + c * 9;

    float qa = 0.f, ka = 0.f, va = 0.f;
#pragma unroll
    for (int kh = 0; kh < 3; kh++) {
        int ih = h + kh - 1;
        if (ih < 0 || ih >= HH) continue;
#pragma unroll
        for (int kw2 = 0; kw2 < 3; kw2++) {
            int iw = wq + kw2 - 1;
            if (iw < 0 || iw >= HH) continue;
            float xv = xp[ih * HH + iw];
            int wi = kh * 3 + kw2;
            qa = fmaf(xv, qwp[wi], qa);
            ka = fmaf(xv, kwp[wi], ka);
            va = fmaf(xv, vwp[wi], va);
        }
    }
    g_yq[idx] = qa * qs + qbe;
    g_yk[idx] = ka * ks + kbe;
    g_yv[idx] = va * vs + vbe;
}

// ---------------- TF32 tensor-core GEMM, cp.async double-buffered ----------------
// C[b][m][p] = sum_k W[m][k] * SRC[b][k][p] (+bias)
// Block 128x112, BK=16, 128 threads (2x2 warps), warp tile 64x56 = 4x7 m16n8k8.
// Single __syncthreads per stage; __launch_bounds__(128,3) caps regs at 168 -> 3 CTAs/SM.

__device__ __forceinline__ uint32_t to_tf32(float x) {
    uint32_t u;
    asm("cvt.rna.tf32.f32 %0, %1;" : "=r"(u) : "f"(x));
    return u;
}

__device__ __forceinline__ void mma_tf32(float* d, const uint32_t* a, const uint32_t* b) {
    asm volatile(
        "mma.sync.aligned.m16n8k8.row.col.f32.tf32.tf32.f32 "
        "{%0,%1,%2,%3}, {%4,%5,%6,%7}, {%8,%9}, {%0,%1,%2,%3};\n"
        : "+f"(d[0]), "+f"(d[1]), "+f"(d[2]), "+f"(d[3])
        : "r"(a[0]), "r"(a[1]), "r"(a[2]), "r"(a[3]), "r"(b[0]), "r"(b[1]));
}

__device__ __forceinline__ void cp16(uint32_t dst, const void* src) {
    asm volatile("cp.async.cg.shared.global [%0], [%1], 16;\n" :: "r"(dst), "l"(src));
}
__device__ __forceinline__ void cpCommit() {
    asm volatile("cp.async.commit_group;\n" ::);
}
template<int N> __device__ __forceinline__ void cpWait() {
    asm volatile("cp.async.wait_group %0;\n" :: "n"(N));
}

__global__ void __launch_bounds__(128, 3)
gemm_tf32_kernel(const float* __restrict__ W,
                 const float* __restrict__ bias,
                 const float* __restrict__ src,
                 float* __restrict__ dst,
                 int Kdim)
{
    __shared__ float As[2][BM * AST];   // [m][k] raw f32
    __shared__ float Bs[2][BK * BST];   // [k][n] raw f32

    int b     = blockIdx.z;
    int nBase = blockIdx.x * BN;
    int mBase = blockIdx.y * BM;

    const float* Bb = src + (size_t)b * Kdim * HW;

    int t    = threadIdx.x;
    int wid  = t >> 5;
    int lane = t & 31;
    int g    = lane >> 2;
    int tig  = lane & 3;
    int m0   = (wid >> 1) * 64;
    int n0   = (wid & 1) * 56;

    const float* aPtr = W + (size_t)(mBase + t) * Kdim;   // thread owns A row m=t

    uint32_t sAb[2], sBb[2];
    sAb[0] = (uint32_t)__cvta_generic_to_shared(&As[0][0]);
    sAb[1] = (uint32_t)__cvta_generic_to_shared(&As[1][0]);
    sBb[0] = (uint32_t)__cvta_generic_to_shared(&Bs[0][0]);
    sBb[1] = (uint32_t)__cvta_generic_to_shared(&Bs[1][0]);

    // B load mapping: 448 float4 chunks per stage (16 rows x 28 chunks), 128 threads
    int bi0  = t;
    int bRow0 = bi0 / 28, bC0 = bi0 - bRow0 * 28;
    int bi1  = t + 128;
    int bRow1 = bi1 / 28, bC1 = bi1 - bRow1 * 28;
    int bi2  = t + 256;
    int bRow2 = bi2 / 28, bC2 = bi2 - bRow2 * 28;
    int bi3  = t + 384;
    int bRow3 = bi3 / 28, bC3 = bi3 - bRow3 * 28;
    bool bAct3 = (bi3 < 448);

    float acc[4][7][4];
#pragma unroll
    for (int i = 0; i < 4; i++)
#pragma unroll
        for (int j = 0; j < 7; j++)
#pragma unroll
            for (int r = 0; r < 4; r++) acc[i][j][r] = 0.f;

    int nStages = Kdim >> 4;

#define LOAD_STAGE(K0, BUF)                                                         \
    {                                                                               \
        uint32_t ad = sAb[BUF] + t * (AST * 4);                                     \
        _Pragma("unroll")                                                           \
        for (int q = 0; q < 4; q++)                                                 \
            cp16(ad + q * 16, aPtr + (K0) + 4 * q);                                 \
        cp16(sBb[BUF] + bRow0 * (BST * 4) + bC0 * 16,                               \
             Bb + (size_t)((K0) + bRow0) * HW + nBase + bC0 * 4);                   \
        cp16(sBb[BUF] + bRow1 * (BST * 4) + bC1 * 16,                               \
             Bb + (size_t)((K0) + bRow1) * HW + nBase + bC1 * 4);                   \
        cp16(sBb[BUF] + bRow2 * (BST * 4) + bC2 * 16,                               \
             Bb + (size_t)((K0) + bRow2) * HW + nBase + bC2 * 4);                   \
        if (bAct3)                                                                  \
            cp16(sBb[BUF] + bRow3 * (BST * 4) + bC3 * 16,                           \
                 Bb + (size_t)((K0) + bRow3) * HW + nBase + bC3 * 4);               \
    }

#define COMPUTE_STAGE(BUF)                                                          \
    {                                                                               \
        _Pragma("unroll")                                                           \
        for (int kk = 0; kk < 2; kk++) {                                            \
            int kb = kk * 8;                                                        \
            uint32_t af[4][4];                                                      \
            uint32_t bf[7][2];                                                      \
            _Pragma("unroll")                                                       \
            for (int im = 0; im < 4; im++) {                                        \
                const float* ap = &As[BUF][(m0 + 16 * im + g) * AST + kb + tig];    \
                af[im][0] = to_tf32(ap[0]);                                         \
                af[im][1] = to_tf32(ap[8 * AST]);                                   \
                af[im][2] = to_tf32(ap[4]);                                         \
                af[im][3] = to_tf32(ap[8 * AST + 4]);                               \
            }                                                                       \
            _Pragma("unroll")                                                       \
            for (int jn = 0; jn < 7; jn++) {                                        \
                const float* bp = &Bs[BUF][(kb + tig) * BST + n0 + 8 * jn + g];     \
                bf[jn][0] = to_tf32(bp[0]);                                         \
                bf[jn][1] = to_tf32(bp[4 * BST]);                                   \
            }                                                                       \
            _Pragma("unroll")                                                       \
            for (int im = 0; im < 4; im++)                                          \
                _Pragma("unroll")                                                   \
                for (int jn = 0; jn < 7; jn++)                                      \
                    mma_tf32(acc[im][jn], af[im], bf[jn]);                          \
        }                                                                           \
    }

    LOAD_STAGE(0, 0);
    cpCommit();

    // Single-sync pipeline:
    //   wait(stage s) -> sync (all done computing s-1) -> issue loads for s+1
    //   into the slot drained at s-1 -> compute s (overlaps in-flight cp.async)
    int buf = 0;
    for (int s = 0; s < nStages; s++) {
        cpWait<0>();
        __syncthreads();
        if (s + 1 < nStages) {
            LOAD_STAGE((s + 1) << 4, buf ^ 1);
            cpCommit();
        }
        COMPUTE_STAGE(buf);
        buf ^= 1;
    }

    // ---- epilogue ----
    float* Cb = dst + (size_t)b * (gridDim.y * BM) * HW;
#pragma unroll
    for (int im = 0; im < 4; im++) {
#pragma unroll
        for (int r2 = 0; r2 < 2; r2++) {
            int m = mBase + m0 + 16 * im + g + 8 * r2;
            float bi = bias ? bias[m] : 0.f;
#pragma unroll
            for (int jn = 0; jn < 7; jn++) {
                int n = nBase + n0 + 8 * jn + 2 * tig;
                float2 val = make_float2(acc[im][jn][2 * r2] + bi,
                                         acc[im][jn][2 * r2 + 1] + bi);
                *(float2*)(Cb + (size_t)m * HW + n) = val;
            }
        }
    }
#undef LOAD_STAGE
#undef COMPUTE_STAGE
}

// ---------------- windowed attention: one CTA per (b, head, window) ----------------
// Warps 0..6 each own 7 consecutive rows -> K/V smem columns read once per 7 rows.
__global__ void attn_kernel(const float* __restrict__ pos_emb)
{
    __shared__ float q_s[64 * 49];    // q^T, reused for o^T
    __shared__ float k_s[64 * 49];
    __shared__ float v_s[64 * 49];
    __shared__ float p_s[49 * 50];
    __shared__ float bias_s[169];

    int t   = threadIdx.x;
    int win = blockIdx.x;
    int h   = blockIdx.y;
    int b   = blockIdx.z;

    int base_hw = ((win >> 3) * 7) * HH + (win & 7) * 7;
    size_t gbase = ((size_t)b * INNER + h * 64) * HW;
    const float* qb = g_q + gbase;
    const float* kb = g_k + gbase;
    const float* vb = g_v + gbase;

    for (int e = t; e < 3136; e += 256) {
        int d = e / 49;
        int j = e - d * 49;
        int off = base_hw + (j / 7) * HH + (j % 7);
        size_t gi = (size_t)d * HW + off;
        q_s[e] = qb[gi];
        k_s[e] = kb[gi];
        v_s[e] = vb[gi];
    }
    if (t < 169) bias_s[t] = pos_emb[t * 8 + h];
    __syncthreads();

    int wid  = t >> 5;
    int lane = t & 31;

    if (wid < 7) {
        int iBase = wid * 7;
        int j0 = lane;
        int j1 = lane + 32;
        int jm = (j1 < 49) ? j1 : 48;

        // ---- QK^T: 7 rows at once, K columns loaded once ----
        float a0[7], a1[7];
#pragma unroll
        for (int r = 0; r < 7; r++) { a0[r] = 0.f; a1[r] = 0.f; }

#pragma unroll 8
        for (int d = 0; d < 64; d++) {
            float kc0 = k_s[d * 49 + j0];
            float kc1 = k_s[d * 49 + jm];
#pragma unroll
            for (int r = 0; r < 7; r++) {
                float qd = q_s[d * 49 + iBase + r];
                a0[r] = fmaf(qd, kc0, a0[r]);
                a1[r] = fmaf(qd, kc1, a1[r]);
            }
        }

        // bias + softmax per row
        int xj0 = j0 / 7, yj0 = j0 - xj0 * 7;
        int xj1 = jm / 7, yj1 = jm - xj1 * 7;
#pragma unroll
        for (int r = 0; r < 7; r++) {
            int i = iBase + r;
            int xi = i / 7, yi = i - xi * 7;
            float v0 = a0[r] * 0.125f + bias_s[(xj0 - xi + 6) * 13 + (yj0 - yi + 6)];
            float v1;
            if (j1 < 49)
                v1 = a1[r] * 0.125f + bias_s[(xj1 - xi + 6) * 13 + (yj1 - yi + 6)];
            else
                v1 = -1e30f;

            float mx = fmaxf(v0, v1);
#pragma unroll
            for (int o = 16; o; o >>= 1) mx = fmaxf(mx, __shfl_xor_sync(0xffffffffu, mx, o));
            float e0 = __expf(v0 - mx);
            float e1 = (j1 < 49) ? __expf(v1 - mx) : 0.f;
            float s = e0 + e1;
#pragma unroll
            for (int o = 16; o; o >>= 1) s += __shfl_xor_sync(0xffffffffu, s, o);
            float inv = 1.f / s;
            p_s[i * 50 + j0] = e0 * inv;
            if (j1 < 49) p_s[i * 50 + j1] = e1 * inv;
        }
        __syncwarp();

        // ---- A @ V: 7 rows at once, V columns loaded once ----
        int d0 = lane, d1 = lane + 32;
        float o0[7], o1[7];
#pragma unroll
        for (int r = 0; r < 7; r++) { o0[r] = 0.f; o1[r] = 0.f; }

#pragma unroll 7
        for (int j = 0; j < 49; j++) {
            float vc0 = v_s[d0 * 49 + j];
            float vc1 = v_s[d1 * 49 + j];
#pragma unroll
            for (int r = 0; r < 7; r++) {
                float p = p_s[(iBase + r) * 50 + j];
                o0[r] = fmaf(p, vc0, o0[r]);
                o1[r] = fmaf(p, vc1, o1[r]);
            }
        }
#pragma unroll
        for (int r = 0; r < 7; r++) {
            q_s[d0 * 49 + iBase + r] = o0[r];
            q_s[d1 * 49 + iBase + r] = o1[r];
        }
    }
    __syncthreads();

    float* ob = g_o + gbase;
    for (int e = t; e < 3136; e += 256) {
        int d = e / 49;
        int j = e - d * 49;
        ob[(size_t)d * HW + base_hw + (j / 7) * HH + (j % 7)] = q_s[e];
    }
}

// ---------------- launch ----------------
extern "C" void kernel_launch(void* const* d_in, const int* in_sizes, int n_in,
                              void* d_out, int out_size)
{
    (void)in_sizes; (void)n_in; (void)out_size;
    const float* x      = (const float*)d_in[0];
    const float* q_dw   = (const float*)d_in[1];
    const float* q_g    = (const float*)d_in[2];
    const float* q_b    = (const float*)d_in[3];
    const float* q_m    = (const float*)d_in[4];
    const float* q_v    = (const float*)d_in[5];
    const float* q_pw   = (const float*)d_in[6];
    const float* k_dw   = (const float*)d_in[7];
    const float* k_g    = (const float*)d_in[8];
    const float* k_b    = (const float*)d_in[9];
    const float* k_m    = (const float*)d_in[10];
    const float* k_v    = (const float*)d_in[11];
    const float* k_pw   = (const float*)d_in[12];
    const float* v_dw   = (const float*)d_in[13];
    const float* v_g    = (const float*)d_in[14];
    const float* v_b    = (const float*)d_in[15];
    const float* v_m    = (const float*)d_in[16];
    const float* v_v    = (const float*)d_in[17];
    const float* v_pw   = (const float*)d_in[18];
    const float* pos    = (const float*)d_in[19];
    const float* out_w  = (const float*)d_in[20];
    const float* out_b  = (const float*)d_in[21];
    float* out          = (float*)d_out;

    float *yq, *yk, *yv, *q, *k, *v, *o;
    cudaGetSymbolAddress((void**)&yq, g_yq);
    cudaGetSymbolAddress((void**)&yk, g_yk);
    cudaGetSymbolAddress((void**)&yv, g_yv);
    cudaGetSymbolAddress((void**)&q,  g_q);
    cudaGetSymbolAddress((void**)&k,  g_k);
    cudaGetSymbolAddress((void**)&v,  g_v);
    cudaGetSymbolAddress((void**)&o,  g_o);

    const int dwBlocks = (BATCH * DIMC * HW) / 256;
    dim3 gemmGridQKV(HW / BN, INNER / BM, BATCH);   // (28, 4, 16)
    dim3 gemmGridOut(HW / BN, DIMC / BM, BATCH);    // (28, 2, 16)
    dim3 attnGrid(64, 8, BATCH);

    dw_bn3_kernel<<<dwBlocks, 256>>>(x,
        q_dw, q_g, q_b, q_m, q_v,
        k_dw, k_g, k_b, k_m, k_v,
        v_dw, v_g, v_b, v_m, v_v);
    gemm_tf32_kernel<<<gemmGridQKV, 128>>>(q_pw, nullptr, yq, q, DIMC);
    gemm_tf32_kernel<<<gemmGridQKV, 128>>>(k_pw, nullptr, yk, k, DIMC);
    gemm_tf32_kernel<<<gemmGridQKV, 128>>>(v_pw, nullptr, yv, v, DIMC);
    attn_kernel<<<attnGrid, 256>>>(pos);
    gemm_tf32_kernel<<<gemmGridOut, 128>>>(out_w, out_b, o, out, INNER);
}